// round 1
// baseline (speedup 1.0000x reference)
#include <cuda_runtime.h>
#include <cuda_bf16.h>

// SST: sst[b, k(b,f,t), t] += coeffs[b,f,t], where k = clip(f + adj, 0, F-1)
// and adj = signbit(x[t+1]) - signbit(x[t]) in {-1,0,+1} (adj=0 at t=T-1).
// Since k is always within {f-1, f, f+1}, the scatter is re-expressed as a
// rolling gather along F: while marching f = 0..F-1 we keep three partial
// output rows (f-1, f, f+1) in registers; after consuming source row f, output
// row f-1 is complete and is stored. Each input element: 1 vector load.
// Each output element: 1 vector store. Minimum-traffic streaming kernel.

constexpr int Bdim = 16;
constexpr int Fdim = 256;
constexpr int Tdim = 8192;
constexpr int TPB  = 128;
constexpr int NSEG = 4;            // F split into 4 segments of 64 rows
constexpr int SEG  = Fdim / NSEG;

__device__ __forceinline__ int sgnbit(float x) {
    return (int)(__float_as_uint(x) >> 31);   // matches atan2(0,x): pi iff sign bit
}

__global__ __launch_bounds__(TPB)
void sst_gather_kernel(const float* __restrict__ in, float* __restrict__ out) {
    const int tc = blockIdx.x * TPB + threadIdx.x;   // t-chunk index (4 floats each)
    const int t0 = tc * 4;
    const int b  = blockIdx.y;
    const int f_start = blockIdx.z * SEG;

    const size_t bofs = (size_t)b * Fdim * Tdim;
    const float* __restrict__ ibase = in  + bofs;
    float*       __restrict__ obase = out + bofs;

    const bool notlast = (t0 + 4) < Tdim;   // does lane 3 have a t+1 neighbor?

    float4 accA = make_float4(0.f, 0.f, 0.f, 0.f);   // output row f-1 (pending)
    float4 accB = accA;                               // output row f
    float4 accC = accA;                               // output row f+1

    #pragma unroll 4
    for (int f = f_start - 1; f <= f_start + SEG; ++f) {
        if (f >= 0 && f < Fdim) {
            const float* row = ibase + (size_t)f * Tdim + t0;
            const float4 v = *reinterpret_cast<const float4*>(row);
            // t+4 neighbor: first element of the adjacent thread's float4 ->
            // guaranteed L1 hit (same cache lines as this warp's vector load).
            const float nx = notlast ? __ldg(row + 4) : 0.0f;

            const int s0 = sgnbit(v.x);
            const int s1 = sgnbit(v.y);
            const int s2 = sgnbit(v.z);
            const int s3 = sgnbit(v.w);
            const int s4 = sgnbit(nx);

            int k0 = f + (s1 - s0);
            int k1 = f + (s2 - s1);
            int k2 = f + (s3 - s2);
            int k3 = notlast ? (f + (s4 - s3)) : f;   // pad: adj=0 at t=T-1

            // clip(k, 0, F-1): only bites at f=0 (k=-1 -> 0) and f=F-1 (k=F -> F-1)
            k0 = max(0, min(Fdim - 1, k0));
            k1 = max(0, min(Fdim - 1, k1));
            k2 = max(0, min(Fdim - 1, k2));
            k3 = max(0, min(Fdim - 1, k3));

            const int fm = f - 1, fp = f + 1;
            accA.x += (k0 == fm) ? v.x : 0.f;
            accB.x += (k0 == f ) ? v.x : 0.f;
            accC.x += (k0 == fp) ? v.x : 0.f;
            accA.y += (k1 == fm) ? v.y : 0.f;
            accB.y += (k1 == f ) ? v.y : 0.f;
            accC.y += (k1 == fp) ? v.y : 0.f;
            accA.z += (k2 == fm) ? v.z : 0.f;
            accB.z += (k2 == f ) ? v.z : 0.f;
            accC.z += (k2 == fp) ? v.z : 0.f;
            accA.w += (k3 == fm) ? v.w : 0.f;
            accB.w += (k3 == f ) ? v.w : 0.f;
            accC.w += (k3 == fp) ? v.w : 0.f;
        }

        const int fout = f - 1;   // row completed by consuming source row f
        if (fout >= f_start && fout < f_start + SEG) {
            *reinterpret_cast<float4*>(obase + (size_t)fout * Tdim + t0) = accA;
        }
        accA = accB;
        accB = accC;
        accC = make_float4(0.f, 0.f, 0.f, 0.f);
    }
}

extern "C" void kernel_launch(void* const* d_in, const int* in_sizes, int n_in,
                              void* d_out, int out_size) {
    const float* coeffs = (const float*)d_in[0];
    float* out = (float*)d_out;

    dim3 grid(Tdim / 4 / TPB, Bdim, NSEG);   // (16, 16, 4) = 1024 CTAs
    dim3 block(TPB);
    sst_gather_kernel<<<grid, block>>>(coeffs, out);
}

// round 2
// speedup vs baseline: 1.2442x; 1.2442x over previous
#include <cuda_runtime.h>
#include <cuda_bf16.h>

// SST: sst[b, k(b,f,t), t] += coeffs[b,f,t], where k = clip(f + adj, 0, F-1)
// and adj = signbit(x[t+1]) - signbit(x[t]) in {-1,0,+1} (adj=0 at t=T-1).
// k is always within {f-1, f, f+1}, so the scatter is a rolling gather along
// F: march f keeping three partial output rows (f-1, f, f+1) in registers;
// after consuming source row f, output row f-1 is complete and stored.
//
// R2 changes vs R1 (latency-bound at occ=40%, DRAM=52%):
//  - NSEG 4->8: grid 2048 CTAs -> ~86% occupancy (R1's 1024 CTAs capped occ
//    at ~43%, leaving HBM at half rate).
//  - neighbor sign via __shfl_down_sync instead of per-thread scalar __ldg
//    (halves LDG issue count; only lane 31 loads, predicated).
//  - boundary clamps hoisted to a per-row uniform branch (f==0 / f==F-1),
//    removing 8 IMNMX per float4 from interior rows (alu pipe was 40%).

constexpr int Bdim = 16;
constexpr int Fdim = 256;
constexpr int Tdim = 8192;
constexpr int TPB  = 128;
constexpr int NSEG = 8;            // F split into 8 segments of 32 rows
constexpr int SEG  = Fdim / NSEG;

__device__ __forceinline__ int sgnbit(float x) {
    return (int)(__float_as_uint(x) >> 31);   // matches angle(): pi iff sign bit
}

__global__ __launch_bounds__(TPB)
void sst_gather_kernel(const float* __restrict__ in, float* __restrict__ out) {
    const int tc = blockIdx.x * TPB + threadIdx.x;   // t-chunk index (4 floats)
    const int t0 = tc * 4;
    const int b  = blockIdx.y;
    const int f_start = blockIdx.z * SEG;
    const int lane = threadIdx.x & 31;

    const size_t bofs = (size_t)b * Fdim * Tdim;
    const float* __restrict__ ibase = in  + bofs;
    float*       __restrict__ obase = out + bofs;

    const bool notlast = (t0 + 4) < Tdim;   // lane-local: has a t+1 neighbor?

    float4 accA = make_float4(0.f, 0.f, 0.f, 0.f);   // output row f-1 (pending)
    float4 accB = accA;                               // output row f
    float4 accC = accA;                               // output row f+1

    #pragma unroll 4
    for (int f = f_start - 1; f <= f_start + SEG; ++f) {
        if (f >= 0 && f < Fdim) {           // uniform across block
            const float* row = ibase + (size_t)f * Tdim + t0;
            const float4 v = *reinterpret_cast<const float4*>(row);

            const int s0 = sgnbit(v.x);
            const int s1 = sgnbit(v.y);
            const int s2 = sgnbit(v.z);
            const int s3 = sgnbit(v.w);

            // t0+4 neighbor sign: lane+1's s0; lane 31 crosses the warp
            // boundary and loads it (L1 hit — same 128B region just fetched).
            int s4 = __shfl_down_sync(0xffffffffu, s0, 1);
            if (lane == 31) {
                s4 = notlast ? sgnbit(__ldg(row + 4)) : s3;  // s4==s3 -> d3=0
            }

            int d0 = s1 - s0;
            int d1 = s2 - s1;
            int d2 = s3 - s2;
            int d3 = notlast ? (s4 - s3) : 0;   // pad: adj=0 at t=T-1

            // clip(k,0,F-1) only bites at the F edges; clipped mass stays in
            // row f (accB), never the ghost row. Uniform branch, rare rows.
            if (f == 0) {
                d0 = max(d0, 0); d1 = max(d1, 0); d2 = max(d2, 0); d3 = max(d3, 0);
            } else if (f == Fdim - 1) {
                d0 = min(d0, 0); d1 = min(d1, 0); d2 = min(d2, 0); d3 = min(d3, 0);
            }

            accA.x += (d0 < 0) ? v.x : 0.f;
            accB.x += (d0 == 0) ? v.x : 0.f;
            accC.x += (d0 > 0) ? v.x : 0.f;
            accA.y += (d1 < 0) ? v.y : 0.f;
            accB.y += (d1 == 0) ? v.y : 0.f;
            accC.y += (d1 > 0) ? v.y : 0.f;
            accA.z += (d2 < 0) ? v.z : 0.f;
            accB.z += (d2 == 0) ? v.z : 0.f;
            accC.z += (d2 > 0) ? v.z : 0.f;
            accA.w += (d3 < 0) ? v.w : 0.f;
            accB.w += (d3 == 0) ? v.w : 0.f;
            accC.w += (d3 > 0) ? v.w : 0.f;
        }

        const int fout = f - 1;   // row completed by consuming source row f
        if (fout >= f_start && fout < f_start + SEG) {
            *reinterpret_cast<float4*>(obase + (size_t)fout * Tdim + t0) = accA;
        }
        accA = accB;
        accB = accC;
        accC = make_float4(0.f, 0.f, 0.f, 0.f);
    }
}

extern "C" void kernel_launch(void* const* d_in, const int* in_sizes, int n_in,
                              void* d_out, int out_size) {
    const float* coeffs = (const float*)d_in[0];
    float* out = (float*)d_out;

    dim3 grid(Tdim / 4 / TPB, Bdim, NSEG);   // (16, 16, 8) = 2048 CTAs
    dim3 block(TPB);
    sst_gather_kernel<<<grid, block>>>(coeffs, out);
}